// round 13
// baseline (speedup 1.0000x reference)
#include <cuda_runtime.h>

// SNN: B=1024, T=4096, 6 -> 10 -> 27 LIF (subtract reset).
// THREE-warp groups serving TWO elements (fusion of R11 SIMD-L1 + R12 pairs):
//   A-warp : layer-1 for both elems SIMD (lanes 0-9 = e0, 16-25 = e1 neurons),
//            one lagged ballot/step serves both; masks -> SMEM (STS.128/4 steps)
//   B0/B1  : per-element phaseA staging (cols 0-9 / 16-25), mask bitfield
//            extraction, table fetch, layer-2 recurrence, output.
// 12 warps/CTA x 128 CTAs = 1536 warps = 3/SMSP. Per-group bar.sync(96)/chunk.

#define T_LEN 4096
#define BETA 0.9f
#define CTA_THREADS 384
#define N_CTAS 128
#define GROUPS 4                        /* per CTA */

#define TABLE_FLOATS (1024 * 27 + 32)   /* rows 0..1023 + zero row 1024 */
#define ZERO_ROW 1024u
#define STG_STRIDE 34                   /* [32 steps][34 cols]; even for STS.64 */
#define STG_BANK (32 * STG_STRIDE)      /* 1088 floats */
#define STG_PER_GROUP (2 * STG_BANK)
#define MB_BANK 36                      /* u32: 32 masks + final + pad */
#define MB_PER_GROUP (2 * MB_BANK)
#define MASK_U32 (GROUPS * MB_PER_GROUP)
#define SMEM_FLOATS (TABLE_FLOATS + MASK_U32 + GROUPS * STG_PER_GROUP)
#define SMEM_BYTES (SMEM_FLOATS * 4)    /* 146,688 B */

typedef unsigned long long u64;

__device__ __forceinline__ u64 pack2(float lo, float hi) {
    u64 r; asm("mov.b64 %0,{%1,%2};" : "=l"(r) : "f"(lo), "f"(hi)); return r;
}
__device__ __forceinline__ u64 mul2(u64 a, u64 b) {
    u64 r; asm("mul.rn.f32x2 %0,%1,%2;" : "=l"(r) : "l"(a), "l"(b)); return r;
}
__device__ __forceinline__ u64 fma2(u64 a, u64 b, u64 c) {
    u64 r; asm("fma.rn.f32x2 %0,%1,%2,%3;" : "=l"(r) : "l"(a), "l"(b), "l"(c)); return r;
}
__device__ __forceinline__ u64 add2(u64 a, u64 b) {
    u64 r; asm("add.rn.f32x2 %0,%1,%2;" : "=l"(r) : "l"(a), "l"(b)); return r;
}
__device__ __forceinline__ float fset_gt1(float a) {
    float r; asm("set.gt.f32.f32 %0,%1,0f3F800000;" : "=f"(r) : "f"(a)); return r;
}
#define GROUP_BAR(g) asm volatile("bar.sync %0, 96;" :: "r"(1 + (g)) : "memory")

// Phase A: 10 neuron currents for this lane's timestep into staging columns
// [base, base+10). Per-half f32x2 rounding == scalar; ascending-k chain from a
// mul, then +b1 == cublas accumulation order (reference-exact).
__device__ __forceinline__ void phaseA_store(const float xv[6],
                                             const u64 w12r[5][6],
                                             const u64 b12r[5],
                                             float* wb, int lane, int base)
{
    u64 xx[6];
#pragma unroll
    for (int c = 0; c < 6; c++) xx[c] = pack2(xv[c], xv[c]);
#pragma unroll
    for (int np = 0; np < 5; np++) {
        u64 a = mul2(xx[0], w12r[np][0]);
#pragma unroll
        for (int c = 1; c < 6; c++)
            a = fma2(xx[c], w12r[np][c], a);
        a = add2(a, b12r[np]);
        *reinterpret_cast<u64*>(&wb[lane * STG_STRIDE + base + 2 * np]) = a;
    }
}

// 4 layer-2 steps: mem = fma(beta,mem,cur) - s ; s = (mem>1) as float.
__device__ __forceinline__ void l2_consume4(const float c[4], float& m2, float& s2)
{
#pragma unroll
    for (int i = 0; i < 4; i++) {
        float a2 = fmaf(BETA, m2, c[i]);
        m2 = __fsub_rn(a2, s2);
        s2 = fset_gt1(m2);
    }
}

__global__ void __launch_bounds__(CTA_THREADS, 1)
snn_kernel(const float* __restrict__ x, const float* __restrict__ W1,
           const float* __restrict__ b1, const float* __restrict__ W2,
           const float* __restrict__ b2, float* __restrict__ out)
{
    extern __shared__ float smem[];
    float* table = smem;                                  // [1024][27] + zero row
    unsigned* maskall = (unsigned*)(smem + TABLE_FLOATS); // [GROUPS][2][36]
    float* stg = smem + TABLE_FLOATS + MASK_U32;          // [GROUPS][2][32*34]

    const int tid   = threadIdx.x;
    const int wid   = tid >> 5;
    const int lane  = tid & 31;
    const bool isA  = (wid < GROUPS);
    const int group = wid & (GROUPS - 1);
    const int erole = (wid >> 2) - 1;     // B-warps: 0 or 1; A: -1

    // Layer-2 lookup table: ascending-n accumulation == reference fma-dot
    // with 0/1 spikes (adding 0.0f is exact).
    for (int e = tid; e < 1024 * 27; e += CTA_THREADS) {
        int v = e / 27;
        int m = e - v * 27;
        float acc = 0.0f;
#pragma unroll
        for (int n = 0; n < 10; n++)
            if (v & (1 << n)) acc = __fadd_rn(acc, W2[m * 10 + n]);
        table[e] = __fadd_rn(acc, b2[m]);
    }
    for (int i = 1024 * 27 + tid; i < TABLE_FLOATS; i += CTA_THREADS)
        table[i] = 0.0f;  // ZERO_ROW (row 1024)

    unsigned* mbase = maskall + group * MB_PER_GROUP;
    float* stg0 = stg + group * STG_PER_GROUP;
    float* stg1 = stg0 + STG_BANK;

    if (isA) {
        // ============ A-warp: layer 1 for BOTH elements (SIMD) ============
        __syncthreads();  // table + B's phaseA(ch0) staging visible

        float m1 = 0.0f, s1 = 0.0f;
        // lanes 0-9: elem0 neurons; 16-25: elem1 neurons; rest garbage (masked)
        const bool vlane = (lane < 10) || (lane >= 16 && lane < 26);
        // ballot(step -1) = (1<<10)|(1<<26): both extracted indices = 1024
        bool pd = (lane == 10) || (lane == 26);
        const bool st_lane = (lane == 0);

#pragma unroll 1
        for (int k = 0; k < 128; k++) {
            const float* rb = (k & 1) ? stg1 : stg0;
            unsigned* mrow = mbase + (k & 1) * MB_BANK;
#pragma unroll
            for (int sb = 0; sb < 8; sb++) {
                float c1r[4];
#pragma unroll
                for (int i = 0; i < 4; i++)
                    c1r[i] = rb[(sb * 4 + i) * STG_STRIDE + lane];
                unsigned mr[4];
#pragma unroll
                for (int i = 0; i < 4; i++) {
                    mr[i] = __ballot_sync(0xffffffffu, pd);  // lagged: no stall
                    float a1 = fmaf(BETA, m1, c1r[i]);
                    m1 = __fsub_rn(a1, s1);
                    s1 = fset_gt1(m1);
                    pd = (m1 > 1.0f) && vlane;  // sink until next ballot
                }
                if (st_lane)
                    *reinterpret_cast<uint4*>(mrow + sb * 4) =
                        make_uint4(mr[0], mr[1], mr[2], mr[3]);
            }
            GROUP_BAR(group);
        }
        // final mask (step 4095) -> bank1 extra slot
        unsigned vf = __ballot_sync(0xffffffffu, pd);
        if (st_lane) mbase[MB_BANK + 32] = vf;
        GROUP_BAR(group);
    } else {
        // ====== B-warp (erole = 0/1): phaseA + layer 2 for one element ======
        const int b = (blockIdx.x * GROUPS + group) * 2 + erole;
        const float* xb = x + (size_t)b * (6 * T_LEN);
        const int base = 16 * erole;          // staging column half
        const int shift = 16 * erole;         // ballot bitfield

        u64 w12r[5][6], b12r[5];
#pragma unroll
        for (int np = 0; np < 5; np++) {
            b12r[np] = pack2(b1[2 * np], b1[2 * np + 1]);
#pragma unroll
            for (int c = 0; c < 6; c++)
                w12r[np][c] = pack2(W1[(2 * np) * 6 + c], W1[(2 * np + 1) * 6 + c]);
        }
        float xv[6];
#pragma unroll
        for (int c = 0; c < 6; c++) xv[c] = xb[c * T_LEN + lane];
        phaseA_store(xv, w12r, b12r, stg0, lane, base);  // chunk 0 -> bank 0
#pragma unroll
        for (int c = 0; c < 6; c++) xv[c] = xb[c * T_LEN + 32 + lane];

        __syncthreads();

        const float* trow = table + lane;
        float m2 = 0.0f, s2 = 0.0f;
        float carry[4] = {0.0f, 0.0f, 0.0f, 0.0f};  // fake zero steps (exact)

#pragma unroll 1
        for (int k = 0; k < 128; k++) {
            // phaseA for chunk k+1 into the other bank; prefetch x
            if (k < 127) {
                float* wb = ((k + 1) & 1) ? stg1 : stg0;
                phaseA_store(xv, w12r, b12r, wb, lane, base);
                int kk = (k + 2 < 128) ? k + 2 : 127;
#pragma unroll
                for (int c = 0; c < 6; c++)
                    xv[c] = xb[c * T_LEN + kk * 32 + lane];
            }
            if (k >= 1) {
                const unsigned* mrow = mbase + ((k - 1) & 1) * MB_BANK;
                uint4 cur = *reinterpret_cast<const uint4*>(mrow);
#pragma unroll
                for (int sb = 0; sb < 8; sb++) {
                    uint4 nxt = cur;
                    if (sb < 7)
                        nxt = *reinterpret_cast<const uint4*>(mrow + (sb + 1) * 4);
                    float f[4];
                    f[0] = trow[((cur.x >> shift) & 0x7FFu) * 27u];
                    f[1] = trow[((cur.y >> shift) & 0x7FFu) * 27u];
                    f[2] = trow[((cur.z >> shift) & 0x7FFu) * 27u];
                    f[3] = trow[((cur.w >> shift) & 0x7FFu) * 27u];
                    l2_consume4(carry, m2, s2);
#pragma unroll
                    for (int i = 0; i < 4; i++) carry[i] = f[i];
                    cur = nxt;
                }
            }
            GROUP_BAR(group);
        }
        GROUP_BAR(group);  // A's bank1 masks + final mask visible

        // Epilogue: chunk 127 (bank 1) + final mask (slot 32)
        {
            const unsigned* mrow = mbase + MB_BANK;
            uint4 cur = *reinterpret_cast<const uint4*>(mrow);
#pragma unroll
            for (int sb = 0; sb < 8; sb++) {
                uint4 nxt = cur;
                if (sb < 7)
                    nxt = *reinterpret_cast<const uint4*>(mrow + (sb + 1) * 4);
                float f[4];
                f[0] = trow[((cur.x >> shift) & 0x7FFu) * 27u];
                f[1] = trow[((cur.y >> shift) & 0x7FFu) * 27u];
                f[2] = trow[((cur.z >> shift) & 0x7FFu) * 27u];
                f[3] = trow[((cur.w >> shift) & 0x7FFu) * 27u];
                l2_consume4(carry, m2, s2);
#pragma unroll
                for (int i = 0; i < 4; i++) carry[i] = f[i];
                cur = nxt;
            }
            float ff = trow[((mrow[32] >> shift) & 0x7FFu) * 27u];  // mask(4095)
            l2_consume4(carry, m2, s2);
            float a2 = fmaf(BETA, m2, ff);
            m2 = __fsub_rn(a2, s2);
            s2 = fset_gt1(m2);
        }

        if (lane < 27)
            out[b * 27 + lane] = s2;
    }
}

extern "C" void kernel_launch(void* const* d_in, const int* in_sizes, int n_in,
                              void* d_out, int out_size)
{
    const float* x  = (const float*)d_in[0];
    const float* W1 = (const float*)d_in[1];
    const float* b1 = (const float*)d_in[2];
    const float* W2 = (const float*)d_in[3];
    const float* b2 = (const float*)d_in[4];
    float* out = (float*)d_out;

    cudaFuncSetAttribute(snn_kernel, cudaFuncAttributeMaxDynamicSharedMemorySize,
                         SMEM_BYTES);

    snn_kernel<<<N_CTAS, CTA_THREADS, SMEM_BYTES>>>(x, W1, b1, W2, b2, out);
}